// round 10
// baseline (speedup 1.0000x reference)
#include <cuda_runtime.h>

// MPSLayer, fused single kernel (R9 structure + barrier-minimized mm/chain).
//   out[b,o]  = s[b]*v[o] + bias[o]
//   s[b]      = prod_n x[b,n]          (local per epilogue block)
//   u         = ones^T @ core_0 @ ... @ core_255
//   Psum[r,o] = sum_l proj[r,l,o]
//   v[o]      = sum_r u[r]*Psum[r,o]
// Tree: 64 blocks ∏4 cores -> D ; blocks 0..15 ∏4 D -> E (row-major) ;
//       block 0: 16-step vector chain via cp.async ring -> u -> v.
// Grid 128 x 256 (blocks 64..127 compute Psum); all co-resident.

#define DD      32
#define N_IN    256
#define BATCH   1024
#define OUT_DIM 512

__device__ __align__(16) float g_D[64 * 1024];
__device__ __align__(16) float g_E[16 * 1024];
__device__ __align__(16) float g_Psum[DD * OUT_DIM];
__device__ __align__(16) float g_v[OUT_DIM];

__device__ int g_cnt_D4[16];     // 4 producers, 1 poller each
__device__ int g_cnt_E;          // 15 producers, 1 poller (block 0)
__device__ int g_cnt_P;          // 64 producers, 1 poller (block 0)
__device__ int g_flag_v_p[128];  // private: 1 writer thread, 1 poller each

// ---- sync primitives --------------------------------------------------------
__device__ __forceinline__ int ld_acq(const int* p) {
    int v;
    asm volatile("ld.acquire.gpu.global.b32 %0, [%1];" : "=r"(v) : "l"(p) : "memory");
    return v;
}
__device__ __forceinline__ int ld_rlx(const int* p) {
    int v;
    asm volatile("ld.relaxed.gpu.global.b32 %0, [%1];" : "=r"(v) : "l"(p) : "memory");
    return v;
}
__device__ __forceinline__ void red_rel_add(int* p, int v) {
    asm volatile("red.release.gpu.global.add.s32 [%0], %1;" :: "l"(p), "r"(v) : "memory");
}
__device__ __forceinline__ void st_relaxed(int* p, int v) {
    asm volatile("st.relaxed.gpu.global.b32 [%0], %1;" :: "l"(p), "r"(v) : "memory");
}
__device__ __forceinline__ void spin_ge(int* cnt, int target) {
    if (threadIdx.x == 0) {
        while (ld_rlx(cnt) < target) { }
        (void)ld_acq(cnt);
    }
    __syncthreads();
}

// ---- cp.async ---------------------------------------------------------------
__device__ __forceinline__ void cpa16(unsigned dst, const float* src) {
    asm volatile("cp.async.ca.shared.global [%0], [%1], 16;" :: "r"(dst), "l"(src));
}
#define CP_COMMIT() asm volatile("cp.async.commit_group;" ::: "memory")
#define CP_WAIT(n)  asm volatile("cp.async.wait_group %0;" :: "n"(n) : "memory")

// ---------------------------------------------------------------------------
// Register-resident 32x32 step: thread owns P[l][4q..4q+3] (l=tid>>3, q=tid&7);
// returns P @ B(smem row-major). Row values gathered by shfl within the 8-lane
// row group.
// ---------------------------------------------------------------------------
__device__ __forceinline__ float4 mm_step_reg(float4 p, const float4* __restrict__ B4,
                                              int lane, int q) {
    float4 acc = make_float4(0.f, 0.f, 0.f, 0.f);
    int grp = lane & 24;
    #pragma unroll
    for (int j = 0; j < 8; ++j) {
        float a; float4 b;
        a = __shfl_sync(0xffffffffu, p.x, grp + j);
        b = B4[(4 * j + 0) * 8 + q];
        acc.x = fmaf(a, b.x, acc.x); acc.y = fmaf(a, b.y, acc.y);
        acc.z = fmaf(a, b.z, acc.z); acc.w = fmaf(a, b.w, acc.w);
        a = __shfl_sync(0xffffffffu, p.y, grp + j);
        b = B4[(4 * j + 1) * 8 + q];
        acc.x = fmaf(a, b.x, acc.x); acc.y = fmaf(a, b.y, acc.y);
        acc.z = fmaf(a, b.z, acc.z); acc.w = fmaf(a, b.w, acc.w);
        a = __shfl_sync(0xffffffffu, p.z, grp + j);
        b = B4[(4 * j + 2) * 8 + q];
        acc.x = fmaf(a, b.x, acc.x); acc.y = fmaf(a, b.y, acc.y);
        acc.z = fmaf(a, b.z, acc.z); acc.w = fmaf(a, b.w, acc.w);
        a = __shfl_sync(0xffffffffu, p.w, grp + j);
        b = B4[(4 * j + 3) * 8 + q];
        acc.x = fmaf(a, b.x, acc.x); acc.y = fmaf(a, b.y, acc.y);
        acc.z = fmaf(a, b.z, acc.z); acc.w = fmaf(a, b.w, acc.w);
    }
    return acc;
}

// Product of 4 consecutive 32x32 matrices (global, row-major), result in regs.
// B1..B3 staged into three DISTINCT buffers, single barrier, 3 fused steps.
// Caller guarantees a __syncthreads() before s1/s2/s3 are reused.
__device__ __forceinline__ float4 mm_chain4_reg(const float4* __restrict__ src4,
                                                float4* s1, float4* s2, float4* s3) {
    int tid = threadIdx.x, lane = tid & 31, q = tid & 7;
    float4 p  = src4[tid];
    float4 b1 = src4[256 + tid];
    float4 b2 = src4[512 + tid];
    float4 b3 = src4[768 + tid];
    s1[tid] = b1;
    s2[tid] = b2;
    s3[tid] = b3;
    __syncthreads();
    p = mm_step_reg(p, s1, lane, q);
    p = mm_step_reg(p, s2, lane, q);
    p = mm_step_reg(p, s3, lane, q);
    return p;
}

// ---------------------------------------------------------------------------
// Chain step, smem-broadcast u: lane owns column `lane` of the row-major stage.
// sUbuf alternates per step (double-buffer) -> no trailing syncwarp needed.
// ---------------------------------------------------------------------------
__device__ __forceinline__ float chain_step_b(float u, const float* __restrict__ stage,
                                              float* __restrict__ sUbuf, int lane) {
    sUbuf[lane] = u;
    __syncwarp();
    const float4* u4 = reinterpret_cast<const float4*>(sUbuf);
    float a0 = 0.f, a1 = 0.f, a2 = 0.f, a3 = 0.f;
    #pragma unroll
    for (int k8 = 0; k8 < 8; ++k8) {
        float4 uu = u4[k8];                       // broadcast (all lanes same addr)
        a0 = fmaf(uu.x, stage[(4 * k8 + 0) * 32 + lane], a0);
        a1 = fmaf(uu.y, stage[(4 * k8 + 1) * 32 + lane], a1);
        a2 = fmaf(uu.z, stage[(4 * k8 + 2) * 32 + lane], a2);
        a3 = fmaf(uu.w, stage[(4 * k8 + 3) * 32 + lane], a3);
    }
    return (a0 + a1) + (a2 + a3);
}

// ---------------------------------------------------------------------------
__global__ void __launch_bounds__(256) fused_mps(
    const float* __restrict__ x, const float* __restrict__ cores,
    const float* __restrict__ proj, const float* __restrict__ bias,
    float* __restrict__ out) {

    __shared__ __align__(16) float sm[4 * 1024];   // 4 ring stages x 4KB
    __shared__ __align__(16) float sUd[2][DD];     // double-buffered u broadcast
    __shared__ __align__(16) float sU[DD];         // final u
    __shared__ float sS[8];
    int tid = threadIdx.x;
    int blk = blockIdx.x;
    int lane = tid & 31;
    int w = tid >> 5;

    // ---- entry prefetches ----------------------------------------------------
    int o4 = tid & 127;
    float4 bi = reinterpret_cast<const float4*>(bias)[o4];
    const float4* x4 = reinterpret_cast<const float4*>(x);
    int xrow = blk * 8 + w;
    float4 xa = x4[xrow * 64 + lane];
    float4 xb = x4[xrow * 64 + 32 + lane];

    float4* stg0 = reinterpret_cast<float4*>(sm);
    float4* stg1 = reinterpret_cast<float4*>(sm + 1024);
    float4* stg2 = reinterpret_cast<float4*>(sm + 2048);
    float4* stg3 = reinterpret_cast<float4*>(sm + 3072);
    unsigned smb = (unsigned)__cvta_generic_to_shared(sm);

    if (blk < 64) {
        // ---- level 1: D[blk] = product of 4 cores
        float4 p = mm_chain4_reg(
            reinterpret_cast<const float4*>(cores) + (size_t)blk * 1024,
            stg1, stg2, stg3);
        reinterpret_cast<float4*>(g_D)[blk * 256 + tid] = p;
        __syncthreads();                 // stores done + stg1..3 reads done
        if (tid == 0) red_rel_add(&g_cnt_D4[blk >> 2], 1);

        if (blk < 16) {
            // ---- level 2: E[blk] = D[4blk] @ .. @ D[4blk+3]
            spin_ge(&g_cnt_D4[blk], 4);  // barrier also guards stg reuse
            if (tid == 0) st_relaxed(&g_cnt_D4[blk], 0);
            float4 e = mm_chain4_reg(
                reinterpret_cast<const float4*>(g_D) + (size_t)blk * 1024,
                stg1, stg2, stg3);
            if (blk > 0) {
                reinterpret_cast<float4*>(g_E)[blk * 256 + tid] = e;   // coalesced
                __syncthreads();
                if (tid == 0) red_rel_add(&g_cnt_E, 1);
            } else {
                stg0[tid] = e;           // E0 straight into ring stage 0
            }
        }
        if (blk == 0) {
            // Psum ready early: sync + prefetch its columns into registers
            spin_ge(&g_cnt_P, 64);       // barrier also orders stg0 writes
            if (tid == 0) st_relaxed(&g_cnt_P, 0);
            float pc0[DD], pc1[DD];
            #pragma unroll
            for (int r = 0; r < DD; ++r) pc0[r] = g_Psum[r * OUT_DIM + tid];
            #pragma unroll
            for (int r = 0; r < DD; ++r) pc1[r] = g_Psum[r * OUT_DIM + tid + 256];

            spin_ge(&g_cnt_E, 15);
            if (tid == 0) st_relaxed(&g_cnt_E, 0);

            if (tid < DD) {                 // warp 0: vector chain
                // prime ring stages 1..3
                #pragma unroll
                for (int m = 1; m <= 3; ++m) {
                    const float* s = g_E + m * 1024 + lane * 4;
                    unsigned d = smb + (unsigned)(m & 3) * 4096 + lane * 16;
                    #pragma unroll
                    for (int i = 0; i < 8; ++i) cpa16(d + i * 512, s + i * 128);
                    CP_COMMIT();
                }
                float u = 1.f;
                #pragma unroll
                for (int n = 0; n < 16; ++n) {
                    if (n >= 1) {
                        if (n <= 13)      CP_WAIT(2);
                        else if (n == 14) CP_WAIT(1);
                        else              CP_WAIT(0);
                        __syncwarp();
                    }
                    int m = n + 3;
                    if (m >= 4 && m < 16) {     // refill freed slot
                        const float* s = g_E + m * 1024 + lane * 4;
                        unsigned d = smb + (unsigned)(m & 3) * 4096 + lane * 16;
                        #pragma unroll
                        for (int i = 0; i < 8; ++i) cpa16(d + i * 512, s + i * 128);
                        CP_COMMIT();
                    }
                    u = chain_step_b(u, sm + (n & 3) * 1024, sUd[n & 1], lane);
                }
                sU[lane] = u;
            }
            __syncthreads();
            // v = u^T Psum (from prefetched registers)
            float a0 = 0.f, a1 = 0.f;
            #pragma unroll
            for (int r = 0; r < DD; ++r) {
                float ur = sU[r];
                a0 = fmaf(ur, pc0[r], a0);
                a1 = fmaf(ur, pc1[r], a1);
            }
            g_v[tid]       = a0;
            g_v[tid + 256] = a1;
            __syncthreads();
            // private release: one flag per consumer block, one writer thread
            if (tid < 128) red_rel_add(&g_flag_v_p[tid], 1);
        }
    } else {
        // ---- Psum[r, half]: blocks 64..127
        int p = blk - 64;
        int r = p >> 1;
        int o = (p & 1) * 256 + tid;
        const float* base = proj + (size_t)r * DD * OUT_DIM + o;
        float acc = 0.f;
        #pragma unroll
        for (int ll = 0; ll < DD; ++ll) acc += base[ll * OUT_DIM];
        g_Psum[r * OUT_DIM + o] = acc;
        __syncthreads();
        if (tid == 0) red_rel_add(&g_cnt_P, 1);
    }

    // ---- epilogue: out[b,o] = s[b]*v[o] + bias[o], 8 rows per block ----------
    float pr = (xa.x * xa.y) * (xa.z * xa.w) * ((xb.x * xb.y) * (xb.z * xb.w));
    #pragma unroll
    for (int off = 16; off; off >>= 1)
        pr *= __shfl_xor_sync(0xffffffffu, pr, off);
    if (lane == 0) sS[w] = pr;

    if (tid == 0) {                       // private flag: single poller
        while (ld_rlx(&g_flag_v_p[blk]) == 0) { }
        (void)ld_acq(&g_flag_v_p[blk]);
        st_relaxed(&g_flag_v_p[blk], 0);  // self-reset for next replay
    }
    __syncthreads();                      // sS ready + v visible

    float4 v = reinterpret_cast<const float4*>(g_v)[o4];
    float4* out4 = reinterpret_cast<float4*>(out);
    int sub = tid >> 7;                   // 0/1
    int b0 = blk * 8;
    #pragma unroll
    for (int i = 0; i < 4; ++i) {
        int row = 2 * i + sub;
        float s = sS[row];
        float4 o;
        o.x = fmaf(s, v.x, bi.x);
        o.y = fmaf(s, v.y, bi.y);
        o.z = fmaf(s, v.z, bi.z);
        o.w = fmaf(s, v.w, bi.w);
        out4[(size_t)(b0 + row) * 128 + o4] = o;
    }
}

// ---------------------------------------------------------------------------
extern "C" void kernel_launch(void* const* d_in, const int* in_sizes, int n_in,
                              void* d_out, int out_size) {
    const float* x     = (const float*)d_in[0];
    const float* cores = (const float*)d_in[1];
    const float* proj  = (const float*)d_in[2];
    const float* bias  = (const float*)d_in[3];
    float* out = (float*)d_out;

    fused_mps<<<128, 256>>>(x, cores, proj, bias, out);
}

// round 11
// speedup vs baseline: 1.1056x; 1.1056x over previous
#include <cuda_runtime.h>

// MPSLayer, fused single kernel (R10 structure + f32x2 packed-FMA matmul).
//   out[b,o]  = s[b]*v[o] + bias[o]
//   s[b]      = prod_n x[b,n]          (local per epilogue block)
//   u         = ones^T @ core_0 @ ... @ core_255
//   Psum[r,o] = sum_l proj[r,l,o]
//   v[o]      = sum_r u[r]*Psum[r,o]
// Tree: 64 blocks ∏4 cores -> D ; blocks 0..15 ∏4 D -> E (row-major) ;
//       block 0: 16-step vector chain via cp.async ring -> u -> v.
// Grid 128 x 256 (blocks 64..127 compute Psum); all co-resident.

#define DD      32
#define N_IN    256
#define BATCH   1024
#define OUT_DIM 512

__device__ __align__(16) float g_D[64 * 1024];
__device__ __align__(16) float g_E[16 * 1024];
__device__ __align__(16) float g_Psum[DD * OUT_DIM];
__device__ __align__(16) float g_v[OUT_DIM];

__device__ int g_cnt_D4[16];     // 4 producers, 1 poller each
__device__ int g_cnt_E;          // 15 producers, 1 poller (block 0)
__device__ int g_cnt_P;          // 64 producers, 1 poller (block 0)
__device__ int g_flag_v_p[128];  // private: 1 writer thread, 1 poller each

// ---- sync primitives --------------------------------------------------------
__device__ __forceinline__ int ld_acq(const int* p) {
    int v;
    asm volatile("ld.acquire.gpu.global.b32 %0, [%1];" : "=r"(v) : "l"(p) : "memory");
    return v;
}
__device__ __forceinline__ int ld_rlx(const int* p) {
    int v;
    asm volatile("ld.relaxed.gpu.global.b32 %0, [%1];" : "=r"(v) : "l"(p) : "memory");
    return v;
}
__device__ __forceinline__ void red_rel_add(int* p, int v) {
    asm volatile("red.release.gpu.global.add.s32 [%0], %1;" :: "l"(p), "r"(v) : "memory");
}
__device__ __forceinline__ void st_relaxed(int* p, int v) {
    asm volatile("st.relaxed.gpu.global.b32 [%0], %1;" :: "l"(p), "r"(v) : "memory");
}
__device__ __forceinline__ void spin_ge(int* cnt, int target) {
    if (threadIdx.x == 0) {
        while (ld_rlx(cnt) < target) { }
        (void)ld_acq(cnt);
    }
    __syncthreads();
}

// ---- cp.async ---------------------------------------------------------------
__device__ __forceinline__ void cpa16(unsigned dst, const float* src) {
    asm volatile("cp.async.ca.shared.global [%0], [%1], 16;" :: "r"(dst), "l"(src));
}
#define CP_COMMIT() asm volatile("cp.async.commit_group;" ::: "memory")
#define CP_WAIT(n)  asm volatile("cp.async.wait_group %0;" :: "n"(n) : "memory")

// ---- packed f32x2 helpers -----------------------------------------------------
__device__ __forceinline__ unsigned long long pack_dup(float a) {
    unsigned long long r;
    asm("mov.b64 %0, {%1, %1};" : "=l"(r) : "f"(a));
    return r;
}
__device__ __forceinline__ void ffma2(unsigned long long& acc, unsigned long long a,
                                      unsigned long long b) {
    asm("fma.rn.f32x2 %0, %1, %2, %0;" : "+l"(acc) : "l"(a), "l"(b));
}

// ---------------------------------------------------------------------------
// Register-resident 32x32 step, packed-FMA form: thread owns P[l][4q..4q+3]
// (l=tid>>3, q=tid&7); returns P @ B(smem row-major). Row values of P gathered
// by shfl within the 8-lane row group; per k: 1 shfl + 1 pack + 2 FFMA2.
// Bit-exact vs the scalar version (f32x2 = two independent fp32 FMAs).
// ---------------------------------------------------------------------------
__device__ __forceinline__ float4 mm_step_reg(float4 p, const float* __restrict__ B,
                                              int lane, int q) {
    const ulonglong2* B2 = reinterpret_cast<const ulonglong2*>(B);
    unsigned long long acc01 = 0ull, acc23 = 0ull;   // (0.0f,0.0f) packed
    int grp = lane & 24;
    #pragma unroll
    for (int j = 0; j < 8; ++j) {
        float a; unsigned long long a2; ulonglong2 bb;
        a = __shfl_sync(0xffffffffu, p.x, grp + j);
        a2 = pack_dup(a);
        bb = B2[(4 * j + 0) * 8 + q];
        ffma2(acc01, a2, bb.x); ffma2(acc23, a2, bb.y);
        a = __shfl_sync(0xffffffffu, p.y, grp + j);
        a2 = pack_dup(a);
        bb = B2[(4 * j + 1) * 8 + q];
        ffma2(acc01, a2, bb.x); ffma2(acc23, a2, bb.y);
        a = __shfl_sync(0xffffffffu, p.z, grp + j);
        a2 = pack_dup(a);
        bb = B2[(4 * j + 2) * 8 + q];
        ffma2(acc01, a2, bb.x); ffma2(acc23, a2, bb.y);
        a = __shfl_sync(0xffffffffu, p.w, grp + j);
        a2 = pack_dup(a);
        bb = B2[(4 * j + 3) * 8 + q];
        ffma2(acc01, a2, bb.x); ffma2(acc23, a2, bb.y);
    }
    float4 r;
    asm("mov.b64 {%0, %1}, %2;" : "=f"(r.x), "=f"(r.y) : "l"(acc01));
    asm("mov.b64 {%0, %1}, %2;" : "=f"(r.z), "=f"(r.w) : "l"(acc23));
    return r;
}

// Product of 4 consecutive 32x32 matrices (global, row-major), result in regs.
// B1..B3 staged into three DISTINCT buffers, single barrier, 3 fused steps.
// Caller guarantees a __syncthreads() before s1/s2/s3 are reused.
__device__ __forceinline__ float4 mm_chain4_reg(const float4* __restrict__ src4,
                                                float4* s1, float4* s2, float4* s3) {
    int tid = threadIdx.x, lane = tid & 31, q = tid & 7;
    float4 p  = src4[tid];
    float4 b1 = src4[256 + tid];
    float4 b2 = src4[512 + tid];
    float4 b3 = src4[768 + tid];
    s1[tid] = b1;
    s2[tid] = b2;
    s3[tid] = b3;
    __syncthreads();
    p = mm_step_reg(p, reinterpret_cast<const float*>(s1), lane, q);
    p = mm_step_reg(p, reinterpret_cast<const float*>(s2), lane, q);
    p = mm_step_reg(p, reinterpret_cast<const float*>(s3), lane, q);
    return p;
}

// ---------------------------------------------------------------------------
// Chain step, smem-broadcast u: lane owns column `lane` of the row-major stage.
// sUbuf alternates per step (double-buffer) -> no trailing syncwarp needed.
// ---------------------------------------------------------------------------
__device__ __forceinline__ float chain_step_b(float u, const float* __restrict__ stage,
                                              float* __restrict__ sUbuf, int lane) {
    sUbuf[lane] = u;
    __syncwarp();
    const float4* u4 = reinterpret_cast<const float4*>(sUbuf);
    float a0 = 0.f, a1 = 0.f, a2 = 0.f, a3 = 0.f;
    #pragma unroll
    for (int k8 = 0; k8 < 8; ++k8) {
        float4 uu = u4[k8];                       // broadcast (all lanes same addr)
        a0 = fmaf(uu.x, stage[(4 * k8 + 0) * 32 + lane], a0);
        a1 = fmaf(uu.y, stage[(4 * k8 + 1) * 32 + lane], a1);
        a2 = fmaf(uu.z, stage[(4 * k8 + 2) * 32 + lane], a2);
        a3 = fmaf(uu.w, stage[(4 * k8 + 3) * 32 + lane], a3);
    }
    return (a0 + a1) + (a2 + a3);
}

// ---------------------------------------------------------------------------
__global__ void __launch_bounds__(256) fused_mps(
    const float* __restrict__ x, const float* __restrict__ cores,
    const float* __restrict__ proj, const float* __restrict__ bias,
    float* __restrict__ out) {

    __shared__ __align__(16) float sm[4 * 1024];   // 4 ring stages x 4KB
    __shared__ __align__(16) float sUd[2][DD];     // double-buffered u broadcast
    __shared__ __align__(16) float sU[DD];         // final u
    __shared__ float sS[8];
    int tid = threadIdx.x;
    int blk = blockIdx.x;
    int lane = tid & 31;
    int w = tid >> 5;

    // ---- entry prefetches ----------------------------------------------------
    int o4 = tid & 127;
    float4 bi = reinterpret_cast<const float4*>(bias)[o4];
    const float4* x4 = reinterpret_cast<const float4*>(x);
    int xrow = blk * 8 + w;
    float4 xa = x4[xrow * 64 + lane];
    float4 xb = x4[xrow * 64 + 32 + lane];

    float4* stg0 = reinterpret_cast<float4*>(sm);
    float4* stg1 = reinterpret_cast<float4*>(sm + 1024);
    float4* stg2 = reinterpret_cast<float4*>(sm + 2048);
    float4* stg3 = reinterpret_cast<float4*>(sm + 3072);
    unsigned smb = (unsigned)__cvta_generic_to_shared(sm);

    if (blk < 64) {
        // ---- level 1: D[blk] = product of 4 cores
        float4 p = mm_chain4_reg(
            reinterpret_cast<const float4*>(cores) + (size_t)blk * 1024,
            stg1, stg2, stg3);
        reinterpret_cast<float4*>(g_D)[blk * 256 + tid] = p;
        __syncthreads();                 // stores done + stg1..3 reads done
        if (tid == 0) red_rel_add(&g_cnt_D4[blk >> 2], 1);

        if (blk < 16) {
            // ---- level 2: E[blk] = D[4blk] @ .. @ D[4blk+3]
            spin_ge(&g_cnt_D4[blk], 4);  // barrier also guards stg reuse
            if (tid == 0) st_relaxed(&g_cnt_D4[blk], 0);
            float4 e = mm_chain4_reg(
                reinterpret_cast<const float4*>(g_D) + (size_t)blk * 1024,
                stg1, stg2, stg3);
            if (blk > 0) {
                reinterpret_cast<float4*>(g_E)[blk * 256 + tid] = e;   // coalesced
                __syncthreads();
                if (tid == 0) red_rel_add(&g_cnt_E, 1);
            } else {
                stg0[tid] = e;           // E0 straight into ring stage 0
            }
        }
        if (blk == 0) {
            // Psum ready early: sync + prefetch its columns into registers
            spin_ge(&g_cnt_P, 64);       // barrier also orders stg0 writes
            if (tid == 0) st_relaxed(&g_cnt_P, 0);
            float pc0[DD], pc1[DD];
            #pragma unroll
            for (int r = 0; r < DD; ++r) pc0[r] = g_Psum[r * OUT_DIM + tid];
            #pragma unroll
            for (int r = 0; r < DD; ++r) pc1[r] = g_Psum[r * OUT_DIM + tid + 256];

            spin_ge(&g_cnt_E, 15);
            if (tid == 0) st_relaxed(&g_cnt_E, 0);

            if (tid < DD) {                 // warp 0: vector chain
                // prime ring stages 1..3
                #pragma unroll
                for (int m = 1; m <= 3; ++m) {
                    const float* s = g_E + m * 1024 + lane * 4;
                    unsigned d = smb + (unsigned)(m & 3) * 4096 + lane * 16;
                    #pragma unroll
                    for (int i = 0; i < 8; ++i) cpa16(d + i * 512, s + i * 128);
                    CP_COMMIT();
                }
                float u = 1.f;
                #pragma unroll
                for (int n = 0; n < 16; ++n) {
                    if (n >= 1) {
                        if (n <= 13)      CP_WAIT(2);
                        else if (n == 14) CP_WAIT(1);
                        else              CP_WAIT(0);
                        __syncwarp();
                    }
                    int m = n + 3;
                    if (m >= 4 && m < 16) {     // refill freed slot
                        const float* s = g_E + m * 1024 + lane * 4;
                        unsigned d = smb + (unsigned)(m & 3) * 4096 + lane * 16;
                        #pragma unroll
                        for (int i = 0; i < 8; ++i) cpa16(d + i * 512, s + i * 128);
                        CP_COMMIT();
                    }
                    u = chain_step_b(u, sm + (n & 3) * 1024, sUd[n & 1], lane);
                }
                sU[lane] = u;
            }
            __syncthreads();
            // v = u^T Psum (from prefetched registers)
            float a0 = 0.f, a1 = 0.f;
            #pragma unroll
            for (int r = 0; r < DD; ++r) {
                float ur = sU[r];
                a0 = fmaf(ur, pc0[r], a0);
                a1 = fmaf(ur, pc1[r], a1);
            }
            g_v[tid]       = a0;
            g_v[tid + 256] = a1;
            __syncthreads();
            // private release: one flag per consumer block, one writer thread
            if (tid < 128) red_rel_add(&g_flag_v_p[tid], 1);
        }
    } else {
        // ---- Psum[r, half]: blocks 64..127
        int p = blk - 64;
        int r = p >> 1;
        int o = (p & 1) * 256 + tid;
        const float* base = proj + (size_t)r * DD * OUT_DIM + o;
        float acc = 0.f;
        #pragma unroll
        for (int ll = 0; ll < DD; ++ll) acc += base[ll * OUT_DIM];
        g_Psum[r * OUT_DIM + o] = acc;
        __syncthreads();
        if (tid == 0) red_rel_add(&g_cnt_P, 1);
    }

    // ---- epilogue: out[b,o] = s[b]*v[o] + bias[o], 8 rows per block ----------
    float pr = (xa.x * xa.y) * (xa.z * xa.w) * ((xb.x * xb.y) * (xb.z * xb.w));
    #pragma unroll
    for (int off = 16; off; off >>= 1)
        pr *= __shfl_xor_sync(0xffffffffu, pr, off);
    if (lane == 0) sS[w] = pr;

    if (tid == 0) {                       // private flag: single poller
        while (ld_rlx(&g_flag_v_p[blk]) == 0) { }
        (void)ld_acq(&g_flag_v_p[blk]);
        st_relaxed(&g_flag_v_p[blk], 0);  // self-reset for next replay
    }
    __syncthreads();                      // sS ready + v visible

    float4 v = reinterpret_cast<const float4*>(g_v)[o4];
    float4* out4 = reinterpret_cast<float4*>(out);
    int sub = tid >> 7;                   // 0/1
    int b0 = blk * 8;
    #pragma unroll
    for (int i = 0; i < 4; ++i) {
        int row = 2 * i + sub;
        float s = sS[row];
        float4 o;
        o.x = fmaf(s, v.x, bi.x);
        o.y = fmaf(s, v.y, bi.y);
        o.z = fmaf(s, v.z, bi.z);
        o.w = fmaf(s, v.w, bi.w);
        out4[(size_t)(b0 + row) * 128 + o4] = o;
    }
}

// ---------------------------------------------------------------------------
extern "C" void kernel_launch(void* const* d_in, const int* in_sizes, int n_in,
                              void* d_out, int out_size) {
    const float* x     = (const float*)d_in[0];
    const float* cores = (const float*)d_in[1];
    const float* proj  = (const float*)d_in[2];
    const float* bias  = (const float*)d_in[3];
    float* out = (float*)d_out;

    fused_mps<<<128, 256>>>(x, cores, proj, bias, out);
}